// round 13
// baseline (speedup 1.0000x reference)
#include <cuda_runtime.h>
#include <cuda_fp16.h>

#define NROWS 204800
#define BN_EPS 1e-5f

#define FD0 100000
#define FD1 1000
#define FD2 100
#define FD3 50
#define PV (FD0 + FD1 + FD2 + FD3)
#define GOFF1 FD0
#define GOFF2 (FD0 + FD1)
#define GOFF3 (FD0 + FD1 + FD2)

#define GRID 592
#define NWARPS (GRID * 8)            // 4736
#define TILE_R 64
#define N_TILES (NROWS / TILE_R)     // 3200
#define NPAIR (NROWS / 2)            // 102400

__device__ __forceinline__ unsigned h2u(__half2 h) {
    return *reinterpret_cast<unsigned*>(&h);
}
__device__ __forceinline__ __half2 u2h(unsigned u) {
    return *reinterpret_cast<__half2*>(&u);
}

// Scratch (device globals; no runtime allocation allowed)
__device__ uint2 g_Gh[(size_t)PV * 32];          // fp16 fused table (P_lo,P_hi | lin,emb)
__device__ float g_A[64 * 8];
__device__ float g_cb[64];
__device__ __half2 g_h1h[(size_t)NROWS * 32];    // h1 fp16: (col c, col c+32)
__device__ __half g_h2h[(size_t)NROWS * 32];     // h2 fp16 row-major
__device__ float g_part1[GRID * 128];
__device__ float g_part2[GRID * 64];
__device__ float g_bn1[128];
__device__ float g_bn2[64];
// Monotonic grid-barrier counters (never reset -> graph-replay safe)
__device__ unsigned g_barA[3];
__device__ unsigned g_barR[3];

// Shared-memory union across phases (max ~28.5KB -> 4 blocks/SM)
struct S1 { float rs[64][8]; float rq[64][8]; float A0s[8][32]; float A1s[8][32]; };
struct S3 { float a[TILE_R * 68]; float wt[64 * 36]; float sc[64]; float sh[64];
            float wsum[256]; float wsq[256]; };
struct S5 { float a[TILE_R * 36]; float wt[32 * 36]; float sc[32]; float sh[32]; };
union __align__(16) USh { S1 s1; S3 s3; S5 s5; float fin[256]; };

// ---------------------------------------------------------------------------
// Fused persistent kernel: setup -> bar0 -> k1 -> bar1(+BN1) -> k3 ->
// bar2(+BN2) -> k5. Monotonic arrive/release barriers; last block finalizes.
// ---------------------------------------------------------------------------
__global__ void __launch_bounds__(256, 4) kFused(
    const float* __restrict__ x,
    const float* __restrict__ emb0, const float* __restrict__ lin0,
    const float* __restrict__ emb1, const float* __restrict__ lin1,
    const float* __restrict__ emb2, const float* __restrict__ lin2,
    const float* __restrict__ emb3, const float* __restrict__ lin3,
    const float* __restrict__ cont_w, const float* __restrict__ cont_b,
    const float* __restrict__ clin_w, const float* __restrict__ clin_b,
    const float* __restrict__ fin_bias,
    const float* __restrict__ w1, const float* __restrict__ b1,
    const float* __restrict__ g1, const float* __restrict__ beta1,
    const float* __restrict__ w2, const float* __restrict__ b2,
    const float* __restrict__ g2, const float* __restrict__ beta2,
    const float* __restrict__ wout, const float* __restrict__ bout,
    float* __restrict__ out) {
    __shared__ USh u;
    __shared__ unsigned s_tgt;
    __shared__ int s_last;

    const unsigned FULL = 0xffffffffu;
    int tid = threadIdx.x;
    int lane = tid & 31, warp = tid >> 5;
    int bid = blockIdx.x;
    int gw = bid * 8 + warp;
    const unsigned GRIDu = (unsigned)gridDim.x;

    // ===== Phase 0: build fp16 fused gather table + cont-fold =====
    {
        const float* emb = 0; const float* lin = 0;
        int V = 0, gOff = 0, colOff = 0, wfirst = 0, nwarp = 1;
        bool table = true;
        if (gw < 4608)      { emb = emb0; lin = lin0; V = FD0; gOff = 0;     colOff = 0;  wfirst = gw;        nwarp = 4608; }
        else if (gw < 4672) { emb = emb1; lin = lin1; V = FD1; gOff = GOFF1; colOff = 32; wfirst = gw - 4608; nwarp = 64; }
        else if (gw < 4676) { emb = emb2; lin = lin2; V = FD2; gOff = GOFF2; colOff = 64; wfirst = gw - 4672; nwarp = 4; }
        else if (gw < 4680) { emb = emb3; lin = lin3; V = FD3; gOff = GOFF3; colOff = 96; wfirst = gw - 4676; nwarp = 4; }
        else table = false;

        if (table) {
            float wa[32], wb[32];
#pragma unroll
            for (int d = 0; d < 32; d++) {
                wa[d] = w1[lane * 384 + colOff + d];
                wb[d] = w1[(lane + 32) * 384 + colOff + d];
            }
            for (int v = wfirst; v < V; v += nwarp) {
                float ev = emb[v * 32 + lane];
                float lv = lin[v * 32 + lane];
                float a0 = 0.f, a1 = 0.f;
#pragma unroll
                for (int d = 0; d < 32; d++) {
                    float e = __shfl_sync(FULL, ev, d);
                    a0 = fmaf(e, wa[d], a0);
                    a1 = fmaf(e, wb[d], a1);
                }
                uint2 pk;
                pk.x = h2u(__floats2half2_rn(a0, a1));
                pk.y = h2u(__floats2half2_rn(lv, ev));
                g_Gh[(size_t)(gOff + v) * 32 + lane] = pk;
            }
        } else if (bid == GRID - 1 && tid < 64) {
            int j = tid;
            float cb = b1[j];
            for (int c = 0; c < 8; c++) {
                float a = 0.f;
#pragma unroll
                for (int d = 0; d < 32; d++) {
                    float w = w1[j * 384 + (4 + c) * 32 + d];
                    a = fmaf(cont_w[c * 32 + d], w, a);
                    cb = fmaf(cont_b[c * 32 + d], w, cb);
                }
                g_A[j * 8 + c] = a;
            }
            g_cb[j] = cb;
        }
    }

    // ---- barrier 0 ----
    __syncthreads();
    if (tid == 0) {
        __threadfence();
        unsigned tk = atomicAdd(&g_barA[0], 1u);
        s_tgt = (tk / GRIDu + 1u) * GRIDu;
        s_last = (tk % GRIDu == GRIDu - 1u) ? 1 : 0;
    }
    __syncthreads();
    if (s_last) {
        if (tid == 0) { __threadfence(); atomicAdd(&g_barR[0], GRIDu); }
    } else if (tid == 0) {
        while (atomicAdd(&g_barR[0], 0u) < s_tgt) __nanosleep(64);
        __threadfence();
    }
    __syncthreads();

    // ===== Phase 1: FM + linear + h1 (2 rows / warp-iter) =====
    {
        // loop-invariant A columns in smem (per-lane layout, conflict-free)
        if (tid < 256) {
            int c = tid >> 5, l = tid & 31;
            u.s1.A0s[c][l] = g_A[l * 8 + c];
            u.s1.A1s[c][l] = g_A[(l + 32) * 8 + c];
        }
        __syncthreads();

        float cw[8], cbv[8], clw[8];
        float finb = fin_bias[lane];
#pragma unroll
        for (int c = 0; c < 8; c++) {
            cw[c] = cont_w[c * 32 + lane];
            cbv[c] = cont_b[c * 32 + lane];
            clw[c] = clin_w[c * 32 + lane];
            finb += clin_b[c * 32 + lane];
        }
        float cb0 = g_cb[lane], cb1 = g_cb[lane + 32];
        float sum0 = 0.f, sq0 = 0.f, sum1 = 0.f, sq1 = 0.f;

        for (int pr = gw; pr < NPAIR; pr += NWARPS) {
            int rA = pr * 2;
            int rB = rA + 1;
            float xv = 0.f;
            if (lane < 24) xv = x[(size_t)rA * 12 + lane];
            int iA0 = (int)__shfl_sync(FULL, xv, 0);
            int iA1 = (int)__shfl_sync(FULL, xv, 1);
            int iA2 = (int)__shfl_sync(FULL, xv, 2);
            int iA3 = (int)__shfl_sync(FULL, xv, 3);
            int iB0 = (int)__shfl_sync(FULL, xv, 12);
            int iB1 = (int)__shfl_sync(FULL, xv, 13);
            int iB2 = (int)__shfl_sync(FULL, xv, 14);
            int iB3 = (int)__shfl_sync(FULL, xv, 15);
            float xcA[8], xcB[8];
#pragma unroll
            for (int c = 0; c < 8; c++) {
                xcA[c] = __shfl_sync(FULL, xv, 4 + c);
                xcB[c] = __shfl_sync(FULL, xv, 16 + c);
            }

            uint2 gA0 = g_Gh[(size_t)iA0 * 32 + lane];
            uint2 gA1 = g_Gh[(size_t)(GOFF1 + iA1) * 32 + lane];
            uint2 gA2 = g_Gh[(size_t)(GOFF2 + iA2) * 32 + lane];
            uint2 gA3 = g_Gh[(size_t)(GOFF3 + iA3) * 32 + lane];
            uint2 gB0 = g_Gh[(size_t)iB0 * 32 + lane];
            uint2 gB1 = g_Gh[(size_t)(GOFF1 + iB1) * 32 + lane];
            uint2 gB2 = g_Gh[(size_t)(GOFF2 + iB2) * 32 + lane];
            uint2 gB3 = g_Gh[(size_t)(GOFF3 + iB3) * 32 + lane];

            // row A
            {
                float2 p0 = __half22float2(u2h(gA0.x)), le0 = __half22float2(u2h(gA0.y));
                float2 p1 = __half22float2(u2h(gA1.x)), le1 = __half22float2(u2h(gA1.y));
                float2 p2 = __half22float2(u2h(gA2.x)), le2 = __half22float2(u2h(gA2.y));
                float2 p3 = __half22float2(u2h(gA3.x)), le3 = __half22float2(u2h(gA3.y));
                float s = le0.y + le1.y + le2.y + le3.y;
                float sq = le0.y * le0.y + le1.y * le1.y + le2.y * le2.y + le3.y * le3.y;
                float lin = finb + le0.x + le1.x + le2.x + le3.x;
#pragma unroll
                for (int c = 0; c < 8; c++) {
                    float e = fmaf(xcA[c], cw[c], cbv[c]);
                    s += e;
                    sq = fmaf(e, e, sq);
                    lin = fmaf(xcA[c], clw[c], lin);
                }
                out[(size_t)rA * 32 + lane] = lin + 0.5f * (s * s - sq);
                float a0 = cb0 + p0.x + p1.x + p2.x + p3.x;
                float a1 = cb1 + p0.y + p1.y + p2.y + p3.y;
#pragma unroll
                for (int c = 0; c < 8; c++) {
                    a0 = fmaf(xcA[c], u.s1.A0s[c][lane], a0);
                    a1 = fmaf(xcA[c], u.s1.A1s[c][lane], a1);
                }
                g_h1h[(size_t)rA * 32 + lane] = __floats2half2_rn(a0, a1);
                sum0 += a0; sq0 = fmaf(a0, a0, sq0);
                sum1 += a1; sq1 = fmaf(a1, a1, sq1);
            }
            // row B
            {
                float2 p0 = __half22float2(u2h(gB0.x)), le0 = __half22float2(u2h(gB0.y));
                float2 p1 = __half22float2(u2h(gB1.x)), le1 = __half22float2(u2h(gB1.y));
                float2 p2 = __half22float2(u2h(gB2.x)), le2 = __half22float2(u2h(gB2.y));
                float2 p3 = __half22float2(u2h(gB3.x)), le3 = __half22float2(u2h(gB3.y));
                float s = le0.y + le1.y + le2.y + le3.y;
                float sq = le0.y * le0.y + le1.y * le1.y + le2.y * le2.y + le3.y * le3.y;
                float lin = finb + le0.x + le1.x + le2.x + le3.x;
#pragma unroll
                for (int c = 0; c < 8; c++) {
                    float e = fmaf(xcB[c], cw[c], cbv[c]);
                    s += e;
                    sq = fmaf(e, e, sq);
                    lin = fmaf(xcB[c], clw[c], lin);
                }
                out[(size_t)rB * 32 + lane] = lin + 0.5f * (s * s - sq);
                float a0 = cb0 + p0.x + p1.x + p2.x + p3.x;
                float a1 = cb1 + p0.y + p1.y + p2.y + p3.y;
#pragma unroll
                for (int c = 0; c < 8; c++) {
                    a0 = fmaf(xcB[c], u.s1.A0s[c][lane], a0);
                    a1 = fmaf(xcB[c], u.s1.A1s[c][lane], a1);
                }
                g_h1h[(size_t)rB * 32 + lane] = __floats2half2_rn(a0, a1);
                sum0 += a0; sq0 = fmaf(a0, a0, sq0);
                sum1 += a1; sq1 = fmaf(a1, a1, sq1);
            }
        }

        __syncthreads();
        u.s1.rs[lane][warp] = sum0; u.s1.rs[lane + 32][warp] = sum1;
        u.s1.rq[lane][warp] = sq0;  u.s1.rq[lane + 32][warp] = sq1;
        __syncthreads();
        int t = tid;
        if (t < 64) {
            float a = 0.f;
#pragma unroll
            for (int w = 0; w < 8; w++) a += u.s1.rs[t][w];
            g_part1[bid * 128 + t] = a;
        } else if (t < 128) {
            float a = 0.f;
#pragma unroll
            for (int w = 0; w < 8; w++) a += u.s1.rq[t - 64][w];
            g_part1[bid * 128 + t] = a;
        }
    }

    // ---- barrier 1 (+ BN1 finalize) ----
    __syncthreads();
    if (tid == 0) {
        __threadfence();
        unsigned tk = atomicAdd(&g_barA[1], 1u);
        s_tgt = (tk / GRIDu + 1u) * GRIDu;
        s_last = (tk % GRIDu == GRIDu - 1u) ? 1 : 0;
    }
    __syncthreads();
    if (s_last) {
        int t = tid;
        int ch = t & 127;
        int half = t >> 7;   // 2 slices of 296 blocks
        float a = 0.f;
        int b0 = half * (GRID / 2);
        for (int b = b0; b < b0 + GRID / 2; b++) a += g_part1[b * 128 + ch];
        u.fin[t] = a;
        __syncthreads();
        if (t < 64) {
            float s = u.fin[t] + u.fin[128 + t];
            float q = u.fin[64 + t] + u.fin[192 + t];
            float mean = s / (float)NROWS;
            float var = q / (float)NROWS - mean * mean;
            float scale = g1[t] * rsqrtf(var + BN_EPS);
            g_bn1[t] = scale;
            g_bn1[64 + t] = beta1[t] - mean * scale;
        }
        __syncthreads();
        if (tid == 0) { __threadfence(); atomicAdd(&g_barR[1], GRIDu); }
    } else if (tid == 0) {
        while (atomicAdd(&g_barR[1], 0u) < s_tgt) __nanosleep(64);
        __threadfence();
    }
    __syncthreads();

    // ===== Phase 2: h2 = relu(bn1(h1)) @ w2^T + b2 (64-row tiles) =====
    {
        int tr = lane >> 3, tj = lane & 7;
        int j0 = tj * 4;
        for (int i = tid; i < 2048; i += 256) {
            int j = i >> 6, k = i & 63;
            u.s3.wt[k * 36 + j] = w2[i];
        }
        if (tid < 64) { u.s3.sc[tid] = g_bn1[tid]; u.s3.sh[tid] = g_bn1[64 + tid]; }
        float bj[4];
#pragma unroll
        for (int c = 0; c < 4; c++) bj[c] = b2[j0 + c];
        __syncthreads();

        float lsum[4] = {0.f, 0.f, 0.f, 0.f}, lsq[4] = {0.f, 0.f, 0.f, 0.f};
        int rbase = warp * 8 + tr;   // 8 rows per warp

        for (int tile = bid; tile < N_TILES; tile += GRID) {
            size_t base = (size_t)tile * TILE_R;
            for (int i = tid; i < TILE_R * 8; i += 256) {
                int r = i >> 3, c4 = (i & 7) * 4;
                uint4 raw = *(const uint4*)&g_h1h[(base + r) * 32 + c4];
                const __half2* hp = (const __half2*)&raw;
                float lo[4], hi[4];
#pragma unroll
                for (int m = 0; m < 4; m++) {
                    float2 f = __half22float2(hp[m]);
                    lo[m] = fmaxf(fmaf(f.x, u.s3.sc[c4 + m], u.s3.sh[c4 + m]), 0.f);
                    hi[m] = fmaxf(fmaf(f.y, u.s3.sc[c4 + m + 32], u.s3.sh[c4 + m + 32]), 0.f);
                }
                *(float4*)&u.s3.a[r * 68 + c4] = make_float4(lo[0], lo[1], lo[2], lo[3]);
                *(float4*)&u.s3.a[r * 68 + 32 + c4] = make_float4(hi[0], hi[1], hi[2], hi[3]);
            }
            __syncthreads();

            float acc[2][4];
#pragma unroll
            for (int i = 0; i < 2; i++)
#pragma unroll
                for (int c = 0; c < 4; c++) acc[i][c] = 0.f;

#pragma unroll 4
            for (int k = 0; k < 64; k += 4) {
                float4 w0 = *(float4*)&u.s3.wt[(k + 0) * 36 + j0];
                float4 w1v = *(float4*)&u.s3.wt[(k + 1) * 36 + j0];
                float4 w2v = *(float4*)&u.s3.wt[(k + 2) * 36 + j0];
                float4 w3 = *(float4*)&u.s3.wt[(k + 3) * 36 + j0];
#pragma unroll
                for (int i = 0; i < 2; i++) {
                    float4 av = *(float4*)&u.s3.a[(rbase + i * 4) * 68 + k];
                    acc[i][0] = fmaf(av.x, w0.x, acc[i][0]);
                    acc[i][1] = fmaf(av.x, w0.y, acc[i][1]);
                    acc[i][2] = fmaf(av.x, w0.z, acc[i][2]);
                    acc[i][3] = fmaf(av.x, w0.w, acc[i][3]);
                    acc[i][0] = fmaf(av.y, w1v.x, acc[i][0]);
                    acc[i][1] = fmaf(av.y, w1v.y, acc[i][1]);
                    acc[i][2] = fmaf(av.y, w1v.z, acc[i][2]);
                    acc[i][3] = fmaf(av.y, w1v.w, acc[i][3]);
                    acc[i][0] = fmaf(av.z, w2v.x, acc[i][0]);
                    acc[i][1] = fmaf(av.z, w2v.y, acc[i][1]);
                    acc[i][2] = fmaf(av.z, w2v.z, acc[i][2]);
                    acc[i][3] = fmaf(av.z, w2v.w, acc[i][3]);
                    acc[i][0] = fmaf(av.w, w3.x, acc[i][0]);
                    acc[i][1] = fmaf(av.w, w3.y, acc[i][1]);
                    acc[i][2] = fmaf(av.w, w3.z, acc[i][2]);
                    acc[i][3] = fmaf(av.w, w3.w, acc[i][3]);
                }
            }

#pragma unroll
            for (int i = 0; i < 2; i++) {
                size_t r = base + rbase + i * 4;
                float v0 = acc[i][0] + bj[0];
                float v1 = acc[i][1] + bj[1];
                float v2 = acc[i][2] + bj[2];
                float v3 = acc[i][3] + bj[3];
                uint2 pk;
                pk.x = h2u(__floats2half2_rn(v0, v1));
                pk.y = h2u(__floats2half2_rn(v2, v3));
                *(uint2*)&g_h2h[r * 32 + j0] = pk;
                lsum[0] += v0; lsq[0] = fmaf(v0, v0, lsq[0]);
                lsum[1] += v1; lsq[1] = fmaf(v1, v1, lsq[1]);
                lsum[2] += v2; lsq[2] = fmaf(v2, v2, lsq[2]);
                lsum[3] += v3; lsq[3] = fmaf(v3, v3, lsq[3]);
            }
            __syncthreads();
        }

#pragma unroll
        for (int c = 0; c < 4; c++) {
            lsum[c] += __shfl_xor_sync(FULL, lsum[c], 8);
            lsum[c] += __shfl_xor_sync(FULL, lsum[c], 16);
            lsq[c] += __shfl_xor_sync(FULL, lsq[c], 8);
            lsq[c] += __shfl_xor_sync(FULL, lsq[c], 16);
        }
        if (tr == 0) {
#pragma unroll
            for (int c = 0; c < 4; c++) {
                u.s3.wsum[warp * 32 + j0 + c] = lsum[c];
                u.s3.wsq[warp * 32 + j0 + c] = lsq[c];
            }
        }
        __syncthreads();
        int t = tid;
        if (t < 32) {
            float s = 0.f;
#pragma unroll
            for (int w = 0; w < 8; w++) s += u.s3.wsum[w * 32 + t];
            g_part2[bid * 64 + t] = s;
        } else if (t < 64) {
            float q = 0.f;
#pragma unroll
            for (int w = 0; w < 8; w++) q += u.s3.wsq[w * 32 + (t - 32)];
            g_part2[bid * 64 + t] = q;
        }
    }

    // ---- barrier 2 (+ BN2 finalize) ----
    __syncthreads();
    if (tid == 0) {
        __threadfence();
        unsigned tk = atomicAdd(&g_barA[2], 1u);
        s_tgt = (tk / GRIDu + 1u) * GRIDu;
        s_last = (tk % GRIDu == GRIDu - 1u) ? 1 : 0;
    }
    __syncthreads();
    if (s_last) {
        int t = tid;
        int ch = t & 63;
        int sl = t >> 6;   // 4 slices of 148 blocks
        float aa = 0.f;
        int b0 = sl * (GRID / 4);
        for (int b = b0; b < b0 + GRID / 4; b++) aa += g_part2[b * 64 + ch];
        u.fin[t] = aa;
        __syncthreads();
        if (t < 32) {
            float s = (u.fin[t] + u.fin[64 + t]) + (u.fin[128 + t] + u.fin[192 + t]);
            float q = (u.fin[32 + t] + u.fin[96 + t]) + (u.fin[160 + t] + u.fin[224 + t]);
            float mean = s / (float)NROWS;
            float var = q / (float)NROWS - mean * mean;
            float scale = g2[t] * rsqrtf(var + BN_EPS);
            g_bn2[t] = scale;
            g_bn2[32 + t] = beta2[t] - mean * scale;
        }
        __syncthreads();
        if (tid == 0) { __threadfence(); atomicAdd(&g_barR[2], GRIDu); }
    } else if (tid == 0) {
        while (atomicAdd(&g_barR[2], 0u) < s_tgt) __nanosleep(64);
        __threadfence();
    }
    __syncthreads();

    // ===== Phase 3: out += relu(bn2(h2)) @ wout^T + bout (64-row tiles) =====
    {
        int tr = lane >> 3, tj = lane & 7;
        int j0 = tj * 4;
        for (int i = tid; i < 1024; i += 256) {
            int j = i >> 5, k = i & 31;
            u.s5.wt[k * 36 + j] = wout[i];
        }
        if (tid < 32) { u.s5.sc[tid] = g_bn2[tid]; u.s5.sh[tid] = g_bn2[32 + tid]; }
        float bj[4];
#pragma unroll
        for (int c = 0; c < 4; c++) bj[c] = bout[j0 + c];
        __syncthreads();

        int rbase = warp * 8 + tr;

        for (int tile = bid; tile < N_TILES; tile += GRID) {
            size_t base = (size_t)tile * TILE_R;
            for (int i = tid; i < TILE_R * 4; i += 256) {
                int r = i >> 2, c8 = (i & 3) * 8;
                uint4 raw = *(const uint4*)&g_h2h[(base + r) * 32 + c8];
                const __half2* hp = (const __half2*)&raw;
                float f[8];
#pragma unroll
                for (int m = 0; m < 4; m++) {
                    float2 p = __half22float2(hp[m]);
                    f[2 * m] = p.x;
                    f[2 * m + 1] = p.y;
                }
#pragma unroll
                for (int m = 0; m < 8; m++)
                    f[m] = fmaxf(fmaf(f[m], u.s5.sc[c8 + m], u.s5.sh[c8 + m]), 0.f);
                *(float4*)&u.s5.a[r * 36 + c8] = make_float4(f[0], f[1], f[2], f[3]);
                *(float4*)&u.s5.a[r * 36 + c8 + 4] = make_float4(f[4], f[5], f[6], f[7]);
            }
            __syncthreads();

            float acc[2][4];
#pragma unroll
            for (int i = 0; i < 2; i++)
#pragma unroll
                for (int c = 0; c < 4; c++) acc[i][c] = 0.f;

#pragma unroll 4
            for (int k = 0; k < 32; k += 4) {
                float4 w0 = *(float4*)&u.s5.wt[(k + 0) * 36 + j0];
                float4 w1v = *(float4*)&u.s5.wt[(k + 1) * 36 + j0];
                float4 w2v = *(float4*)&u.s5.wt[(k + 2) * 36 + j0];
                float4 w3 = *(float4*)&u.s5.wt[(k + 3) * 36 + j0];
#pragma unroll
                for (int i = 0; i < 2; i++) {
                    float4 av = *(float4*)&u.s5.a[(rbase + i * 4) * 36 + k];
                    acc[i][0] = fmaf(av.x, w0.x, acc[i][0]);
                    acc[i][1] = fmaf(av.x, w0.y, acc[i][1]);
                    acc[i][2] = fmaf(av.x, w0.z, acc[i][2]);
                    acc[i][3] = fmaf(av.x, w0.w, acc[i][3]);
                    acc[i][0] = fmaf(av.y, w1v.x, acc[i][0]);
                    acc[i][1] = fmaf(av.y, w1v.y, acc[i][1]);
                    acc[i][2] = fmaf(av.y, w1v.z, acc[i][2]);
                    acc[i][3] = fmaf(av.y, w1v.w, acc[i][3]);
                    acc[i][0] = fmaf(av.z, w2v.x, acc[i][0]);
                    acc[i][1] = fmaf(av.z, w2v.y, acc[i][1]);
                    acc[i][2] = fmaf(av.z, w2v.z, acc[i][2]);
                    acc[i][3] = fmaf(av.z, w2v.w, acc[i][3]);
                    acc[i][0] = fmaf(av.w, w3.x, acc[i][0]);
                    acc[i][1] = fmaf(av.w, w3.y, acc[i][1]);
                    acc[i][2] = fmaf(av.w, w3.z, acc[i][2]);
                    acc[i][3] = fmaf(av.w, w3.w, acc[i][3]);
                }
            }

#pragma unroll
            for (int i = 0; i < 2; i++) {
                size_t r = base + rbase + i * 4;
                float4 o = *(const float4*)&out[r * 32 + j0];
                o.x += acc[i][0] + bj[0];
                o.y += acc[i][1] + bj[1];
                o.z += acc[i][2] + bj[2];
                o.w += acc[i][3] + bj[3];
                *(float4*)&out[r * 32 + j0] = o;
            }
            __syncthreads();
        }
    }
}

// ---------------------------------------------------------------------------
// Input order (setup_inputs dict insertion): x, emb0, lin0, emb1, lin1,
// emb2, lin2, emb3, lin3, cont_w, cont_b, clin_w, clin_b, fin_bias,
// w1, b1, g1, beta1, w2, b2, g2, beta2, w_out, b_out
// ---------------------------------------------------------------------------
extern "C" void kernel_launch(void* const* d_in, const int* in_sizes, int n_in,
                              void* d_out, int out_size) {
    const float* x      = (const float*)d_in[0];
    const float* emb0   = (const float*)d_in[1];
    const float* lin0   = (const float*)d_in[2];
    const float* emb1   = (const float*)d_in[3];
    const float* lin1   = (const float*)d_in[4];
    const float* emb2   = (const float*)d_in[5];
    const float* lin2   = (const float*)d_in[6];
    const float* emb3   = (const float*)d_in[7];
    const float* lin3   = (const float*)d_in[8];
    const float* cont_w = (const float*)d_in[9];
    const float* cont_b = (const float*)d_in[10];
    const float* clin_w = (const float*)d_in[11];
    const float* clin_b = (const float*)d_in[12];
    const float* fin_b  = (const float*)d_in[13];
    const float* w1     = (const float*)d_in[14];
    const float* b1     = (const float*)d_in[15];
    const float* g1     = (const float*)d_in[16];
    const float* beta1  = (const float*)d_in[17];
    const float* w2     = (const float*)d_in[18];
    const float* b2     = (const float*)d_in[19];
    const float* g2     = (const float*)d_in[20];
    const float* beta2  = (const float*)d_in[21];
    const float* w_out  = (const float*)d_in[22];
    const float* b_out  = (const float*)d_in[23];
    float* out = (float*)d_out;

    kFused<<<GRID, 256>>>(x, emb0, lin0, emb1, lin1, emb2, lin2, emb3, lin3,
                          cont_w, cont_b, clin_w, clin_b, fin_b,
                          w1, b1, g1, beta1, w2, b2, g2, beta2,
                          w_out, b_out, out);
}

// round 14
// speedup vs baseline: 1.1422x; 1.1422x over previous
#include <cuda_runtime.h>
#include <cuda_fp16.h>

#define NROWS 204800
#define BN_EPS 1e-5f

#define FD0 100000
#define FD1 1000
#define FD2 100
#define FD3 50
#define PV (FD0 + FD1 + FD2 + FD3)
#define GOFF1 FD0
#define GOFF2 (FD0 + FD1)
#define GOFF3 (FD0 + FD1 + FD2)

#define GRID 444
#define NWARPS (GRID * 8)            // 3552
#define TILE_R 128
#define N_TILES (NROWS / TILE_R)     // 1600
#define NPAIR (NROWS / 2)            // 102400

__device__ __forceinline__ unsigned h2u(__half2 h) {
    return *reinterpret_cast<unsigned*>(&h);
}
__device__ __forceinline__ __half2 u2h(unsigned u) {
    return *reinterpret_cast<__half2*>(&u);
}

// Scratch (device globals; no runtime allocation allowed)
__device__ uint2 g_Gh[(size_t)PV * 32];          // fp16 fused table (P_lo,P_hi | lin,emb)
__device__ float g_A[64 * 8];
__device__ float g_cb[64];
__device__ __half2 g_h1h[(size_t)NROWS * 32];    // h1 fp16: (col c, col c+32)
__device__ __half g_h2h[(size_t)NROWS * 32];     // h2 fp16 row-major
__device__ float g_part1[GRID * 128];
__device__ float g_part2[GRID * 64];
__device__ float g_bn1[128];
__device__ float g_bn2[64];
// Monotonic grid-barrier counters (never reset -> graph-replay safe)
__device__ unsigned g_barA[3];
__device__ unsigned g_barR[3];

// Shared-memory union across phases
struct S1 { float rs[64][8]; float rq[64][8]; };
struct S3 { float a[TILE_R * 68]; float wt[64 * 36]; float sc[64]; float sh[64];
            float wsum[256]; float wsq[256]; };
struct S5 { float a[TILE_R * 36]; float wt[32 * 36]; float sc[32]; float sh[32]; };
union __align__(16) USh { S1 s1; S3 s3; S5 s5; float fin[256]; };

// ---------------------------------------------------------------------------
// Fused persistent kernel: setup -> bar0 -> k1 -> bar1(+BN1) -> k3 ->
// bar2(+BN2) -> k5. Barriers: monotonic arrive/release, last block finalizes.
// ---------------------------------------------------------------------------
__global__ void __launch_bounds__(256, 3) kFused(
    const float* __restrict__ x,
    const float* __restrict__ emb0, const float* __restrict__ lin0,
    const float* __restrict__ emb1, const float* __restrict__ lin1,
    const float* __restrict__ emb2, const float* __restrict__ lin2,
    const float* __restrict__ emb3, const float* __restrict__ lin3,
    const float* __restrict__ cont_w, const float* __restrict__ cont_b,
    const float* __restrict__ clin_w, const float* __restrict__ clin_b,
    const float* __restrict__ fin_bias,
    const float* __restrict__ w1, const float* __restrict__ b1,
    const float* __restrict__ g1, const float* __restrict__ beta1,
    const float* __restrict__ w2, const float* __restrict__ b2,
    const float* __restrict__ g2, const float* __restrict__ beta2,
    const float* __restrict__ wout, const float* __restrict__ bout,
    float* __restrict__ out) {
    __shared__ USh u;
    __shared__ unsigned s_tgt;
    __shared__ int s_last;

    const unsigned FULL = 0xffffffffu;
    int tid = threadIdx.x;
    int lane = tid & 31, warp = tid >> 5;
    int bid = blockIdx.x;
    int gw = bid * 8 + warp;
    const unsigned GRIDu = (unsigned)gridDim.x;

    // ===== Phase 0: build fp16 fused gather table + cont-fold =====
    {
        const float* emb = 0; const float* lin = 0;
        int V = 0, gOff = 0, colOff = 0, wfirst = 0, nwarp = 1;
        bool table = true;
        if (gw < 3472)      { emb = emb0; lin = lin0; V = FD0; gOff = 0;     colOff = 0;  wfirst = gw;        nwarp = 3472; }
        else if (gw < 3536) { emb = emb1; lin = lin1; V = FD1; gOff = GOFF1; colOff = 32; wfirst = gw - 3472; nwarp = 64; }
        else if (gw < 3540) { emb = emb2; lin = lin2; V = FD2; gOff = GOFF2; colOff = 64; wfirst = gw - 3536; nwarp = 4; }
        else if (gw < 3544) { emb = emb3; lin = lin3; V = FD3; gOff = GOFF3; colOff = 96; wfirst = gw - 3540; nwarp = 4; }
        else table = false;

        if (table) {
            float wa[32], wb[32];
#pragma unroll
            for (int d = 0; d < 32; d++) {
                wa[d] = w1[lane * 384 + colOff + d];
                wb[d] = w1[(lane + 32) * 384 + colOff + d];
            }
            for (int v = wfirst; v < V; v += nwarp) {
                float ev = emb[v * 32 + lane];
                float lv = lin[v * 32 + lane];
                float a0 = 0.f, a1 = 0.f;
#pragma unroll
                for (int d = 0; d < 32; d++) {
                    float e = __shfl_sync(FULL, ev, d);
                    a0 = fmaf(e, wa[d], a0);
                    a1 = fmaf(e, wb[d], a1);
                }
                uint2 pk;
                pk.x = h2u(__floats2half2_rn(a0, a1));
                pk.y = h2u(__floats2half2_rn(lv, ev));
                g_Gh[(size_t)(gOff + v) * 32 + lane] = pk;
            }
        } else if (tid < 64) {
            // last block: cont-fold into w1
            int j = tid;
            float cb = b1[j];
            for (int c = 0; c < 8; c++) {
                float a = 0.f;
#pragma unroll
                for (int d = 0; d < 32; d++) {
                    float w = w1[j * 384 + (4 + c) * 32 + d];
                    a = fmaf(cont_w[c * 32 + d], w, a);
                    cb = fmaf(cont_b[c * 32 + d], w, cb);
                }
                g_A[j * 8 + c] = a;
            }
            g_cb[j] = cb;
        }
    }

    // ---- barrier 0 ----
    __syncthreads();
    if (tid == 0) {
        __threadfence();
        unsigned tk = atomicAdd(&g_barA[0], 1u);
        s_tgt = (tk / GRIDu + 1u) * GRIDu;
        s_last = (tk % GRIDu == GRIDu - 1u) ? 1 : 0;
    }
    __syncthreads();
    if (s_last) {
        if (tid == 0) { __threadfence(); atomicAdd(&g_barR[0], GRIDu); }
    } else if (tid == 0) {
        while (atomicAdd(&g_barR[0], 0u) < s_tgt) __nanosleep(64);
        __threadfence();
    }
    __syncthreads();

    // ===== Phase 1: FM + linear + h1 (2 rows / warp-iter, x prefetched) =====
    {
        float cw[8], cbv[8], clw[8], A0[8], A1[8];
        float finb = fin_bias[lane];
#pragma unroll
        for (int c = 0; c < 8; c++) {
            cw[c] = cont_w[c * 32 + lane];
            cbv[c] = cont_b[c * 32 + lane];
            clw[c] = clin_w[c * 32 + lane];
            finb += clin_b[c * 32 + lane];
            A0[c] = g_A[lane * 8 + c];
            A1[c] = g_A[(lane + 32) * 8 + c];
        }
        float cb0 = g_cb[lane], cb1 = g_cb[lane + 32];
        float sum0 = 0.f, sq0 = 0.f, sum1 = 0.f, sq1 = 0.f;

        // prefetch first x row-pair
        float xv = 0.f;
        if (gw < NPAIR && lane < 24) xv = x[(size_t)gw * 24 + lane];

        for (int pr = gw; pr < NPAIR; pr += NWARPS) {
            int rA = pr * 2;
            int rB = rA + 1;
            int iA0 = (int)__shfl_sync(FULL, xv, 0);
            int iA1 = (int)__shfl_sync(FULL, xv, 1);
            int iA2 = (int)__shfl_sync(FULL, xv, 2);
            int iA3 = (int)__shfl_sync(FULL, xv, 3);
            int iB0 = (int)__shfl_sync(FULL, xv, 12);
            int iB1 = (int)__shfl_sync(FULL, xv, 13);
            int iB2 = (int)__shfl_sync(FULL, xv, 14);
            int iB3 = (int)__shfl_sync(FULL, xv, 15);
            float xcA[8], xcB[8];
#pragma unroll
            for (int c = 0; c < 8; c++) {
                xcA[c] = __shfl_sync(FULL, xv, 4 + c);
                xcB[c] = __shfl_sync(FULL, xv, 16 + c);
            }

            // issue all 8 gathers
            uint2 gA0 = g_Gh[(size_t)iA0 * 32 + lane];
            uint2 gA1 = g_Gh[(size_t)(GOFF1 + iA1) * 32 + lane];
            uint2 gA2 = g_Gh[(size_t)(GOFF2 + iA2) * 32 + lane];
            uint2 gA3 = g_Gh[(size_t)(GOFF3 + iA3) * 32 + lane];
            uint2 gB0 = g_Gh[(size_t)iB0 * 32 + lane];
            uint2 gB1 = g_Gh[(size_t)(GOFF1 + iB1) * 32 + lane];
            uint2 gB2 = g_Gh[(size_t)(GOFF2 + iB2) * 32 + lane];
            uint2 gB3 = g_Gh[(size_t)(GOFF3 + iB3) * 32 + lane];

            // prefetch next iteration's x while gathers are in flight
            float xvn = 0.f;
            int prn = pr + NWARPS;
            if (prn < NPAIR && lane < 24) xvn = x[(size_t)prn * 24 + lane];

            // row A
            {
                float2 p0 = __half22float2(u2h(gA0.x)), le0 = __half22float2(u2h(gA0.y));
                float2 p1 = __half22float2(u2h(gA1.x)), le1 = __half22float2(u2h(gA1.y));
                float2 p2 = __half22float2(u2h(gA2.x)), le2 = __half22float2(u2h(gA2.y));
                float2 p3 = __half22float2(u2h(gA3.x)), le3 = __half22float2(u2h(gA3.y));
                float s = le0.y + le1.y + le2.y + le3.y;
                float sq = le0.y * le0.y + le1.y * le1.y + le2.y * le2.y + le3.y * le3.y;
                float lin = finb + le0.x + le1.x + le2.x + le3.x;
#pragma unroll
                for (int c = 0; c < 8; c++) {
                    float e = fmaf(xcA[c], cw[c], cbv[c]);
                    s += e;
                    sq = fmaf(e, e, sq);
                    lin = fmaf(xcA[c], clw[c], lin);
                }
                out[(size_t)rA * 32 + lane] = lin + 0.5f * (s * s - sq);
                float a0 = cb0 + p0.x + p1.x + p2.x + p3.x;
                float a1 = cb1 + p0.y + p1.y + p2.y + p3.y;
#pragma unroll
                for (int c = 0; c < 8; c++) {
                    a0 = fmaf(xcA[c], A0[c], a0);
                    a1 = fmaf(xcA[c], A1[c], a1);
                }
                g_h1h[(size_t)rA * 32 + lane] = __floats2half2_rn(a0, a1);
                sum0 += a0; sq0 = fmaf(a0, a0, sq0);
                sum1 += a1; sq1 = fmaf(a1, a1, sq1);
            }
            // row B
            {
                float2 p0 = __half22float2(u2h(gB0.x)), le0 = __half22float2(u2h(gB0.y));
                float2 p1 = __half22float2(u2h(gB1.x)), le1 = __half22float2(u2h(gB1.y));
                float2 p2 = __half22float2(u2h(gB2.x)), le2 = __half22float2(u2h(gB2.y));
                float2 p3 = __half22float2(u2h(gB3.x)), le3 = __half22float2(u2h(gB3.y));
                float s = le0.y + le1.y + le2.y + le3.y;
                float sq = le0.y * le0.y + le1.y * le1.y + le2.y * le2.y + le3.y * le3.y;
                float lin = finb + le0.x + le1.x + le2.x + le3.x;
#pragma unroll
                for (int c = 0; c < 8; c++) {
                    float e = fmaf(xcB[c], cw[c], cbv[c]);
                    s += e;
                    sq = fmaf(e, e, sq);
                    lin = fmaf(xcB[c], clw[c], lin);
                }
                out[(size_t)rB * 32 + lane] = lin + 0.5f * (s * s - sq);
                float a0 = cb0 + p0.x + p1.x + p2.x + p3.x;
                float a1 = cb1 + p0.y + p1.y + p2.y + p3.y;
#pragma unroll
                for (int c = 0; c < 8; c++) {
                    a0 = fmaf(xcB[c], A0[c], a0);
                    a1 = fmaf(xcB[c], A1[c], a1);
                }
                g_h1h[(size_t)rB * 32 + lane] = __floats2half2_rn(a0, a1);
                sum0 += a0; sq0 = fmaf(a0, a0, sq0);
                sum1 += a1; sq1 = fmaf(a1, a1, sq1);
            }
            xv = xvn;
        }

        __syncthreads();
        u.s1.rs[lane][warp] = sum0; u.s1.rs[lane + 32][warp] = sum1;
        u.s1.rq[lane][warp] = sq0;  u.s1.rq[lane + 32][warp] = sq1;
        __syncthreads();
        int t = tid;
        if (t < 64) {
            float a = 0.f;
#pragma unroll
            for (int w = 0; w < 8; w++) a += u.s1.rs[t][w];
            g_part1[bid * 128 + t] = a;
        } else if (t < 128) {
            float a = 0.f;
#pragma unroll
            for (int w = 0; w < 8; w++) a += u.s1.rq[t - 64][w];
            g_part1[bid * 128 + t] = a;
        }
    }

    // ---- barrier 1 (+ BN1 finalize by last block) ----
    __syncthreads();
    if (tid == 0) {
        __threadfence();
        unsigned tk = atomicAdd(&g_barA[1], 1u);
        s_tgt = (tk / GRIDu + 1u) * GRIDu;
        s_last = (tk % GRIDu == GRIDu - 1u) ? 1 : 0;
    }
    __syncthreads();
    if (s_last) {
        int t = tid;
        int ch = t & 127;
        int half = t >> 7;   // 2 slices of 222 blocks
        float a = 0.f;
        int b0 = half * (GRID / 2);
        for (int b = b0; b < b0 + GRID / 2; b++) a += g_part1[b * 128 + ch];
        u.fin[t] = a;
        __syncthreads();
        if (t < 64) {
            float s = u.fin[t] + u.fin[128 + t];
            float q = u.fin[64 + t] + u.fin[192 + t];
            float mean = s / (float)NROWS;
            float var = q / (float)NROWS - mean * mean;
            float scale = g1[t] * rsqrtf(var + BN_EPS);
            g_bn1[t] = scale;
            g_bn1[64 + t] = beta1[t] - mean * scale;
        }
        __syncthreads();
        if (tid == 0) { __threadfence(); atomicAdd(&g_barR[1], GRIDu); }
    } else if (tid == 0) {
        while (atomicAdd(&g_barR[1], 0u) < s_tgt) __nanosleep(64);
        __threadfence();
    }
    __syncthreads();

    // ===== Phase 2: h2 = relu(bn1(h1)) @ w2^T + b2 (smem-tiled FFMA) =====
    {
        int tr = lane >> 3, tj = lane & 7;
        int j0 = tj * 4;
        for (int i = tid; i < 2048; i += 256) {
            int j = i >> 6, k = i & 63;
            u.s3.wt[k * 36 + j] = w2[i];
        }
        if (tid < 64) { u.s3.sc[tid] = g_bn1[tid]; u.s3.sh[tid] = g_bn1[64 + tid]; }
        float bj[4];
#pragma unroll
        for (int c = 0; c < 4; c++) bj[c] = b2[j0 + c];
        __syncthreads();

        float lsum[4] = {0.f, 0.f, 0.f, 0.f}, lsq[4] = {0.f, 0.f, 0.f, 0.f};
        int rbase = warp * 16 + tr;

        for (int tile = bid; tile < N_TILES; tile += GRID) {
            size_t base = (size_t)tile * TILE_R;
            for (int i = tid; i < TILE_R * 8; i += 256) {
                int r = i >> 3, c4 = (i & 7) * 4;
                uint4 raw = *(const uint4*)&g_h1h[(base + r) * 32 + c4];
                const __half2* hp = (const __half2*)&raw;
                float lo[4], hi[4];
#pragma unroll
                for (int m = 0; m < 4; m++) {
                    float2 f = __half22float2(hp[m]);
                    lo[m] = fmaxf(fmaf(f.x, u.s3.sc[c4 + m], u.s3.sh[c4 + m]), 0.f);
                    hi[m] = fmaxf(fmaf(f.y, u.s3.sc[c4 + m + 32], u.s3.sh[c4 + m + 32]), 0.f);
                }
                *(float4*)&u.s3.a[r * 68 + c4] = make_float4(lo[0], lo[1], lo[2], lo[3]);
                *(float4*)&u.s3.a[r * 68 + 32 + c4] = make_float4(hi[0], hi[1], hi[2], hi[3]);
            }
            __syncthreads();

            float acc[4][4];
#pragma unroll
            for (int i = 0; i < 4; i++)
#pragma unroll
                for (int c = 0; c < 4; c++) acc[i][c] = 0.f;

#pragma unroll 4
            for (int k = 0; k < 64; k += 4) {
                float4 w0 = *(float4*)&u.s3.wt[(k + 0) * 36 + j0];
                float4 w1v = *(float4*)&u.s3.wt[(k + 1) * 36 + j0];
                float4 w2v = *(float4*)&u.s3.wt[(k + 2) * 36 + j0];
                float4 w3 = *(float4*)&u.s3.wt[(k + 3) * 36 + j0];
#pragma unroll
                for (int i = 0; i < 4; i++) {
                    float4 av = *(float4*)&u.s3.a[(rbase + i * 4) * 68 + k];
                    acc[i][0] = fmaf(av.x, w0.x, acc[i][0]);
                    acc[i][1] = fmaf(av.x, w0.y, acc[i][1]);
                    acc[i][2] = fmaf(av.x, w0.z, acc[i][2]);
                    acc[i][3] = fmaf(av.x, w0.w, acc[i][3]);
                    acc[i][0] = fmaf(av.y, w1v.x, acc[i][0]);
                    acc[i][1] = fmaf(av.y, w1v.y, acc[i][1]);
                    acc[i][2] = fmaf(av.y, w1v.z, acc[i][2]);
                    acc[i][3] = fmaf(av.y, w1v.w, acc[i][3]);
                    acc[i][0] = fmaf(av.z, w2v.x, acc[i][0]);
                    acc[i][1] = fmaf(av.z, w2v.y, acc[i][1]);
                    acc[i][2] = fmaf(av.z, w2v.z, acc[i][2]);
                    acc[i][3] = fmaf(av.z, w2v.w, acc[i][3]);
                    acc[i][0] = fmaf(av.w, w3.x, acc[i][0]);
                    acc[i][1] = fmaf(av.w, w3.y, acc[i][1]);
                    acc[i][2] = fmaf(av.w, w3.z, acc[i][2]);
                    acc[i][3] = fmaf(av.w, w3.w, acc[i][3]);
                }
            }

#pragma unroll
            for (int i = 0; i < 4; i++) {
                size_t r = base + rbase + i * 4;
                float v0 = acc[i][0] + bj[0];
                float v1 = acc[i][1] + bj[1];
                float v2 = acc[i][2] + bj[2];
                float v3 = acc[i][3] + bj[3];
                uint2 pk;
                pk.x = h2u(__floats2half2_rn(v0, v1));
                pk.y = h2u(__floats2half2_rn(v2, v3));
                *(uint2*)&g_h2h[r * 32 + j0] = pk;
                lsum[0] += v0; lsq[0] = fmaf(v0, v0, lsq[0]);
                lsum[1] += v1; lsq[1] = fmaf(v1, v1, lsq[1]);
                lsum[2] += v2; lsq[2] = fmaf(v2, v2, lsq[2]);
                lsum[3] += v3; lsq[3] = fmaf(v3, v3, lsq[3]);
            }
            __syncthreads();
        }

#pragma unroll
        for (int c = 0; c < 4; c++) {
            lsum[c] += __shfl_xor_sync(FULL, lsum[c], 8);
            lsum[c] += __shfl_xor_sync(FULL, lsum[c], 16);
            lsq[c] += __shfl_xor_sync(FULL, lsq[c], 8);
            lsq[c] += __shfl_xor_sync(FULL, lsq[c], 16);
        }
        if (tr == 0) {
#pragma unroll
            for (int c = 0; c < 4; c++) {
                u.s3.wsum[warp * 32 + j0 + c] = lsum[c];
                u.s3.wsq[warp * 32 + j0 + c] = lsq[c];
            }
        }
        __syncthreads();
        int t = tid;
        if (t < 32) {
            float s = 0.f;
#pragma unroll
            for (int w = 0; w < 8; w++) s += u.s3.wsum[w * 32 + t];
            g_part2[bid * 64 + t] = s;
        } else if (t < 64) {
            float q = 0.f;
#pragma unroll
            for (int w = 0; w < 8; w++) q += u.s3.wsq[w * 32 + (t - 32)];
            g_part2[bid * 64 + t] = q;
        }
    }

    // ---- barrier 2 (+ BN2 finalize by last block) ----
    __syncthreads();
    if (tid == 0) {
        __threadfence();
        unsigned tk = atomicAdd(&g_barA[2], 1u);
        s_tgt = (tk / GRIDu + 1u) * GRIDu;
        s_last = (tk % GRIDu == GRIDu - 1u) ? 1 : 0;
    }
    __syncthreads();
    if (s_last) {
        int t = tid;
        int ch = t & 63;
        int sl = t >> 6;   // 4 slices of 111 blocks
        float aa = 0.f;
        int b0 = sl * (GRID / 4);
        for (int b = b0; b < b0 + GRID / 4; b++) aa += g_part2[b * 64 + ch];
        u.fin[t] = aa;
        __syncthreads();
        if (t < 32) {
            float s = (u.fin[t] + u.fin[64 + t]) + (u.fin[128 + t] + u.fin[192 + t]);
            float q = (u.fin[32 + t] + u.fin[96 + t]) + (u.fin[160 + t] + u.fin[224 + t]);
            float mean = s / (float)NROWS;
            float var = q / (float)NROWS - mean * mean;
            float scale = g2[t] * rsqrtf(var + BN_EPS);
            g_bn2[t] = scale;
            g_bn2[32 + t] = beta2[t] - mean * scale;
        }
        __syncthreads();
        if (tid == 0) { __threadfence(); atomicAdd(&g_barR[2], GRIDu); }
    } else if (tid == 0) {
        while (atomicAdd(&g_barR[2], 0u) < s_tgt) __nanosleep(64);
        __threadfence();
    }
    __syncthreads();

    // ===== Phase 3: out += relu(bn2(h2)) @ wout^T + bout =====
    {
        int tr = lane >> 3, tj = lane & 7;
        int j0 = tj * 4;
        for (int i = tid; i < 1024; i += 256) {
            int j = i >> 5, k = i & 31;
            u.s5.wt[k * 36 + j] = wout[i];
        }
        if (tid < 32) { u.s5.sc[tid] = g_bn2[tid]; u.s5.sh[tid] = g_bn2[32 + tid]; }
        float bj[4];
#pragma unroll
        for (int c = 0; c < 4; c++) bj[c] = bout[j0 + c];
        __syncthreads();

        int rbase = warp * 16 + tr;

        for (int tile = bid; tile < N_TILES; tile += GRID) {
            size_t base = (size_t)tile * TILE_R;
            for (int i = tid; i < TILE_R * 4; i += 256) {
                int r = i >> 2, c8 = (i & 3) * 8;
                uint4 raw = *(const uint4*)&g_h2h[(base + r) * 32 + c8];
                const __half2* hp = (const __half2*)&raw;
                float f[8];
#pragma unroll
                for (int m = 0; m < 4; m++) {
                    float2 p = __half22float2(hp[m]);
                    f[2 * m] = p.x;
                    f[2 * m + 1] = p.y;
                }
#pragma unroll
                for (int m = 0; m < 8; m++)
                    f[m] = fmaxf(fmaf(f[m], u.s5.sc[c8 + m], u.s5.sh[c8 + m]), 0.f);
                *(float4*)&u.s5.a[r * 36 + c8] = make_float4(f[0], f[1], f[2], f[3]);
                *(float4*)&u.s5.a[r * 36 + c8 + 4] = make_float4(f[4], f[5], f[6], f[7]);
            }
            __syncthreads();

            float acc[4][4];
#pragma unroll
            for (int i = 0; i < 4; i++)
#pragma unroll
                for (int c = 0; c < 4; c++) acc[i][c] = 0.f;

#pragma unroll 4
            for (int k = 0; k < 32; k += 4) {
                float4 w0 = *(float4*)&u.s5.wt[(k + 0) * 36 + j0];
                float4 w1v = *(float4*)&u.s5.wt[(k + 1) * 36 + j0];
                float4 w2v = *(float4*)&u.s5.wt[(k + 2) * 36 + j0];
                float4 w3 = *(float4*)&u.s5.wt[(k + 3) * 36 + j0];
#pragma unroll
                for (int i = 0; i < 4; i++) {
                    float4 av = *(float4*)&u.s5.a[(rbase + i * 4) * 36 + k];
                    acc[i][0] = fmaf(av.x, w0.x, acc[i][0]);
                    acc[i][1] = fmaf(av.x, w0.y, acc[i][1]);
                    acc[i][2] = fmaf(av.x, w0.z, acc[i][2]);
                    acc[i][3] = fmaf(av.x, w0.w, acc[i][3]);
                    acc[i][0] = fmaf(av.y, w1v.x, acc[i][0]);
                    acc[i][1] = fmaf(av.y, w1v.y, acc[i][1]);
                    acc[i][2] = fmaf(av.y, w1v.z, acc[i][2]);
                    acc[i][3] = fmaf(av.y, w1v.w, acc[i][3]);
                    acc[i][0] = fmaf(av.z, w2v.x, acc[i][0]);
                    acc[i][1] = fmaf(av.z, w2v.y, acc[i][1]);
                    acc[i][2] = fmaf(av.z, w2v.z, acc[i][2]);
                    acc[i][3] = fmaf(av.z, w2v.w, acc[i][3]);
                    acc[i][0] = fmaf(av.w, w3.x, acc[i][0]);
                    acc[i][1] = fmaf(av.w, w3.y, acc[i][1]);
                    acc[i][2] = fmaf(av.w, w3.z, acc[i][2]);
                    acc[i][3] = fmaf(av.w, w3.w, acc[i][3]);
                }
            }

#pragma unroll
            for (int i = 0; i < 4; i++) {
                size_t r = base + rbase + i * 4;
                float4 o = *(const float4*)&out[r * 32 + j0];
                o.x += acc[i][0] + bj[0];
                o.y += acc[i][1] + bj[1];
                o.z += acc[i][2] + bj[2];
                o.w += acc[i][3] + bj[3];
                *(float4*)&out[r * 32 + j0] = o;
            }
            __syncthreads();
        }
    }
}

// ---------------------------------------------------------------------------
// Input order (setup_inputs dict insertion): x, emb0, lin0, emb1, lin1,
// emb2, lin2, emb3, lin3, cont_w, cont_b, clin_w, clin_b, fin_bias,
// w1, b1, g1, beta1, w2, b2, g2, beta2, w_out, b_out
// ---------------------------------------------------------------------------
extern "C" void kernel_launch(void* const* d_in, const int* in_sizes, int n_in,
                              void* d_out, int out_size) {
    const float* x      = (const float*)d_in[0];
    const float* emb0   = (const float*)d_in[1];
    const float* lin0   = (const float*)d_in[2];
    const float* emb1   = (const float*)d_in[3];
    const float* lin1   = (const float*)d_in[4];
    const float* emb2   = (const float*)d_in[5];
    const float* lin2   = (const float*)d_in[6];
    const float* emb3   = (const float*)d_in[7];
    const float* lin3   = (const float*)d_in[8];
    const float* cont_w = (const float*)d_in[9];
    const float* cont_b = (const float*)d_in[10];
    const float* clin_w = (const float*)d_in[11];
    const float* clin_b = (const float*)d_in[12];
    const float* fin_b  = (const float*)d_in[13];
    const float* w1     = (const float*)d_in[14];
    const float* b1     = (const float*)d_in[15];
    const float* g1     = (const float*)d_in[16];
    const float* beta1  = (const float*)d_in[17];
    const float* w2     = (const float*)d_in[18];
    const float* b2     = (const float*)d_in[19];
    const float* g2     = (const float*)d_in[20];
    const float* beta2  = (const float*)d_in[21];
    const float* w_out  = (const float*)d_in[22];
    const float* b_out  = (const float*)d_in[23];
    float* out = (float*)d_out;

    kFused<<<GRID, 256>>>(x, emb0, lin0, emb1, lin1, emb2, lin2, emb3, lin3,
                          cont_w, cont_b, clin_w, clin_b, fin_b,
                          w1, b1, g1, beta1, w2, b2, g2, beta2,
                          w_out, b_out, out);
}

// round 15
// speedup vs baseline: 1.2450x; 1.0900x over previous
#include <cuda_runtime.h>
#include <cuda_fp16.h>

#define NROWS 204800
#define BN_EPS 1e-5f

#define FD0 100000
#define FD1 1000
#define FD2 100
#define FD3 50
#define PV (FD0 + FD1 + FD2 + FD3)
#define GOFF1 FD0
#define GOFF2 (FD0 + FD1)
#define GOFF3 (FD0 + FD1 + FD2)

#define GRID 592
#define NWARPS (GRID * 8)            // 4736
#define TILE_R 128
#define N_TILES (NROWS / TILE_R)     // 1600

__device__ __forceinline__ unsigned h2u(__half2 h) {
    return *reinterpret_cast<unsigned*>(&h);
}
__device__ __forceinline__ __half2 u2h(unsigned u) {
    return *reinterpret_cast<__half2*>(&u);
}

// Scratch (device globals; no runtime allocation allowed)
// Table word layout: word0 = (P_lo, lin), word1 = (P_hi, emb)  [fp16 pairs]
__device__ uint2 g_Gh[(size_t)PV * 32];
__device__ float g_A[64 * 8];
__device__ float g_cb[64];
__device__ __half2 g_h1h[(size_t)NROWS * 32];    // h1 fp16: (col c, col c+32)
__device__ __half g_h2h[(size_t)NROWS * 32];     // h2 fp16 row-major
__device__ float g_part1[GRID * 128];
__device__ float g_part2[GRID * 64];
__device__ float g_bn1[128];
__device__ float g_bn2[64];
// Monotonic grid-barrier counters (never reset -> graph-replay safe)
__device__ unsigned g_barA[3];
__device__ unsigned g_barR[3];

// Shared-memory union across phases (46.6KB; 4 blocks/SM => 186KB/SM)
struct S1 { float rs[64][8]; float rq[64][8]; };
struct S3 { float a[TILE_R * 68]; float wt[64 * 36]; float sc[64]; float sh[64];
            float wsum[256]; float wsq[256]; };
struct S5 { float a[TILE_R * 36]; float wt[32 * 36]; float sc[32]; float sh[32]; };
union __align__(16) USh { S1 s1; S3 s3; S5 s5; float fin[256]; };

// ---------------------------------------------------------------------------
// Fused persistent kernel, 4 blocks/SM (regs forced <=64).
// Phase0 (table, warp-pair halves) -> bar0 -> Phase1 (FM+lin+h1, 1 row/iter)
// -> bar1(+BN1) -> Phase2 (GEMM h2) -> bar2(+BN2) -> Phase3 (GEMM out).
// ---------------------------------------------------------------------------
__global__ void __launch_bounds__(256, 4) kFused(
    const float* __restrict__ x,
    const float* __restrict__ emb0, const float* __restrict__ lin0,
    const float* __restrict__ emb1, const float* __restrict__ lin1,
    const float* __restrict__ emb2, const float* __restrict__ lin2,
    const float* __restrict__ emb3, const float* __restrict__ lin3,
    const float* __restrict__ cont_w, const float* __restrict__ cont_b,
    const float* __restrict__ clin_w, const float* __restrict__ clin_b,
    const float* __restrict__ fin_bias,
    const float* __restrict__ w1, const float* __restrict__ b1,
    const float* __restrict__ g1, const float* __restrict__ beta1,
    const float* __restrict__ w2, const float* __restrict__ b2,
    const float* __restrict__ g2, const float* __restrict__ beta2,
    const float* __restrict__ wout, const float* __restrict__ bout,
    float* __restrict__ out) {
    __shared__ USh u;
    __shared__ unsigned s_tgt;
    __shared__ int s_last;

    const unsigned FULL = 0xffffffffu;
    int tid = threadIdx.x;
    int lane = tid & 31, warp = tid >> 5;
    int bid = blockIdx.x;
    int gw = bid * 8 + warp;
    const unsigned GRIDu = (unsigned)gridDim.x;

    // ===== Phase 0: fp16 fused table, each warp computes ONE half =====
    {
        const float* emb = 0; const float* lin = 0;
        int V = 0, gOff = 0, colOff = 0, vfirst = 0, vstep = 1;
        int mode = 0;   // 0: table, 1: cont-fold, 2: idle
        if (gw < 4608)      { emb = emb0; lin = lin0; V = FD0; gOff = 0;     colOff = 0;  vfirst = gw >> 1;          vstep = 2304; }
        else if (gw < 4704) { emb = emb1; lin = lin1; V = FD1; gOff = GOFF1; colOff = 32; vfirst = (gw - 4608) >> 1; vstep = 48; }
        else if (gw < 4712) { emb = emb2; lin = lin2; V = FD2; gOff = GOFF2; colOff = 64; vfirst = (gw - 4704) >> 1; vstep = 4; }
        else if (gw < 4720) { emb = emb3; lin = lin3; V = FD3; gOff = GOFF3; colOff = 96; vfirst = (gw - 4712) >> 1; vstep = 4; }
        else if (gw < 4722) mode = 1;
        else mode = 2;

        if (mode == 0) {
            int half = gw & 1;     // 0 -> (P_lo, lin) word; 1 -> (P_hi, emb) word
            float wv[32];
#pragma unroll
            for (int d = 0; d < 32; d++)
                wv[d] = w1[(lane + 32 * half) * 384 + colOff + d];
            unsigned* gword = ((unsigned*)g_Gh) + half;
            for (int v = vfirst; v < V; v += vstep) {
                float ev = emb[v * 32 + lane];
                float acc = 0.f;
#pragma unroll
                for (int d = 0; d < 32; d++)
                    acc = fmaf(__shfl_sync(FULL, ev, d), wv[d], acc);
                float other = half ? ev : lin[v * 32 + lane];
                gword[(size_t)(gOff + v) * 64 + lane * 2] =
                    h2u(__floats2half2_rn(acc, other));
            }
        } else if (mode == 1) {
            int j = (gw - 4720) * 32 + lane;   // 0..63
            float cb = b1[j];
            for (int c = 0; c < 8; c++) {
                float a = 0.f;
#pragma unroll
                for (int d = 0; d < 32; d++) {
                    float w = w1[j * 384 + (4 + c) * 32 + d];
                    a = fmaf(cont_w[c * 32 + d], w, a);
                    cb = fmaf(cont_b[c * 32 + d], w, cb);
                }
                g_A[j * 8 + c] = a;
            }
            g_cb[j] = cb;
        }
    }

    // ---- barrier 0 ----
    __syncthreads();
    if (tid == 0) {
        __threadfence();
        unsigned tk = atomicAdd(&g_barA[0], 1u);
        s_tgt = (tk / GRIDu + 1u) * GRIDu;
        s_last = (tk % GRIDu == GRIDu - 1u) ? 1 : 0;
    }
    __syncthreads();
    if (s_last) {
        if (tid == 0) { __threadfence(); atomicAdd(&g_barR[0], GRIDu); }
    } else if (tid == 0) {
        while (atomicAdd(&g_barR[0], 0u) < s_tgt) __nanosleep(64);
        __threadfence();
    }
    __syncthreads();

    // ===== Phase 1: FM + linear + h1 (1 row/iter, low regs) =====
    {
        float cw[8], cbv[8], clw[8];
        __half2 A01[8];
        float finb = fin_bias[lane];
#pragma unroll
        for (int c = 0; c < 8; c++) {
            cw[c] = cont_w[c * 32 + lane];
            cbv[c] = cont_b[c * 32 + lane];
            clw[c] = clin_w[c * 32 + lane];
            finb += clin_b[c * 32 + lane];
            A01[c] = __floats2half2_rn(g_A[lane * 8 + c], g_A[(lane + 32) * 8 + c]);
        }
        float cb0 = g_cb[lane], cb1 = g_cb[lane + 32];
        float sum0 = 0.f, sq0 = 0.f, sum1 = 0.f, sq1 = 0.f;

        float xv = 0.f;
        if (gw < NROWS && lane < 12) xv = x[(size_t)gw * 12 + lane];

        for (int r = gw; r < NROWS; r += NWARPS) {
            int i0 = (int)__shfl_sync(FULL, xv, 0);
            int i1 = (int)__shfl_sync(FULL, xv, 1);
            int i2 = (int)__shfl_sync(FULL, xv, 2);
            int i3 = (int)__shfl_sync(FULL, xv, 3);

            uint2 g0 = g_Gh[(size_t)i0 * 32 + lane];
            uint2 g1v = g_Gh[(size_t)(GOFF1 + i1) * 32 + lane];
            uint2 g2v = g_Gh[(size_t)(GOFF2 + i2) * 32 + lane];
            uint2 g3 = g_Gh[(size_t)(GOFF3 + i3) * 32 + lane];

            // prefetch next row's x while gathers are in flight
            float xvn = 0.f;
            int rn = r + NWARPS;
            if (rn < NROWS && lane < 12) xvn = x[(size_t)rn * 12 + lane];

            float s = 0.f, sq = 0.f, lin = finb;
            __half2 ch = __floats2half2_rn(0.f, 0.f);
#pragma unroll
            for (int c = 0; c < 8; c++) {
                float xc = __shfl_sync(FULL, xv, 4 + c);
                float e = fmaf(xc, cw[c], cbv[c]);
                s += e;
                sq = fmaf(e, e, sq);
                lin = fmaf(xc, clw[c], lin);
                ch = __hfma2(__float2half2_rn(xc), A01[c], ch);
            }

            // decode gathers: d0=(P_lo,lin), d1=(P_hi,emb)
            float2 d00 = __half22float2(u2h(g0.x)), d01 = __half22float2(u2h(g0.y));
            float2 d10 = __half22float2(u2h(g1v.x)), d11 = __half22float2(u2h(g1v.y));
            float2 d20 = __half22float2(u2h(g2v.x)), d21 = __half22float2(u2h(g2v.y));
            float2 d30 = __half22float2(u2h(g3.x)), d31 = __half22float2(u2h(g3.y));

            s += d01.y + d11.y + d21.y + d31.y;
            sq += d01.y * d01.y + d11.y * d11.y + d21.y * d21.y + d31.y * d31.y;
            lin += d00.y + d10.y + d20.y + d30.y;
            out[(size_t)r * 32 + lane] = lin + 0.5f * (s * s - sq);

            float2 chf = __half22float2(ch);
            float a0 = cb0 + chf.x + d00.x + d10.x + d20.x + d30.x;
            float a1 = cb1 + chf.y + d01.x + d11.x + d21.x + d31.x;
            g_h1h[(size_t)r * 32 + lane] = __floats2half2_rn(a0, a1);
            sum0 += a0; sq0 = fmaf(a0, a0, sq0);
            sum1 += a1; sq1 = fmaf(a1, a1, sq1);
            xv = xvn;
        }

        __syncthreads();
        u.s1.rs[lane][warp] = sum0; u.s1.rs[lane + 32][warp] = sum1;
        u.s1.rq[lane][warp] = sq0;  u.s1.rq[lane + 32][warp] = sq1;
        __syncthreads();
        int t = tid;
        if (t < 64) {
            float a = 0.f;
#pragma unroll
            for (int w = 0; w < 8; w++) a += u.s1.rs[t][w];
            g_part1[bid * 128 + t] = a;
        } else if (t < 128) {
            float a = 0.f;
#pragma unroll
            for (int w = 0; w < 8; w++) a += u.s1.rq[t - 64][w];
            g_part1[bid * 128 + t] = a;
        }
    }

    // ---- barrier 1 (+ BN1 finalize by last block) ----
    __syncthreads();
    if (tid == 0) {
        __threadfence();
        unsigned tk = atomicAdd(&g_barA[1], 1u);
        s_tgt = (tk / GRIDu + 1u) * GRIDu;
        s_last = (tk % GRIDu == GRIDu - 1u) ? 1 : 0;
    }
    __syncthreads();
    if (s_last) {
        int t = tid;
        int ch = t & 127;
        int half = t >> 7;   // 2 slices of 296 blocks
        float a = 0.f;
        int b0 = half * (GRID / 2);
        for (int b = b0; b < b0 + GRID / 2; b++) a += g_part1[b * 128 + ch];
        u.fin[t] = a;
        __syncthreads();
        if (t < 64) {
            float s = u.fin[t] + u.fin[128 + t];
            float q = u.fin[64 + t] + u.fin[192 + t];
            float mean = s / (float)NROWS;
            float var = q / (float)NROWS - mean * mean;
            float scale = g1[t] * rsqrtf(var + BN_EPS);
            g_bn1[t] = scale;
            g_bn1[64 + t] = beta1[t] - mean * scale;
        }
        __syncthreads();
        if (tid == 0) { __threadfence(); atomicAdd(&g_barR[1], GRIDu); }
    } else if (tid == 0) {
        while (atomicAdd(&g_barR[1], 0u) < s_tgt) __nanosleep(64);
        __threadfence();
    }
    __syncthreads();

    // ===== Phase 2: h2 = relu(bn1(h1)) @ w2^T + b2 (smem-tiled FFMA) =====
    {
        int tr = lane >> 3, tj = lane & 7;
        int j0 = tj * 4;
        for (int i = tid; i < 2048; i += 256) {
            int j = i >> 6, k = i & 63;
            u.s3.wt[k * 36 + j] = w2[i];
        }
        if (tid < 64) { u.s3.sc[tid] = g_bn1[tid]; u.s3.sh[tid] = g_bn1[64 + tid]; }
        float bj[4];
#pragma unroll
        for (int c = 0; c < 4; c++) bj[c] = b2[j0 + c];
        __syncthreads();

        float lsum[4] = {0.f, 0.f, 0.f, 0.f}, lsq[4] = {0.f, 0.f, 0.f, 0.f};
        int rbase = warp * 16 + tr;

        for (int tile = bid; tile < N_TILES; tile += GRID) {
            size_t base = (size_t)tile * TILE_R;
            for (int i = tid; i < TILE_R * 8; i += 256) {
                int r = i >> 3, c4 = (i & 7) * 4;
                uint4 raw = *(const uint4*)&g_h1h[(base + r) * 32 + c4];
                const __half2* hp = (const __half2*)&raw;
                float lo[4], hi[4];
#pragma unroll
                for (int m = 0; m < 4; m++) {
                    float2 f = __half22float2(hp[m]);
                    lo[m] = fmaxf(fmaf(f.x, u.s3.sc[c4 + m], u.s3.sh[c4 + m]), 0.f);
                    hi[m] = fmaxf(fmaf(f.y, u.s3.sc[c4 + m + 32], u.s3.sh[c4 + m + 32]), 0.f);
                }
                *(float4*)&u.s3.a[r * 68 + c4] = make_float4(lo[0], lo[1], lo[2], lo[3]);
                *(float4*)&u.s3.a[r * 68 + 32 + c4] = make_float4(hi[0], hi[1], hi[2], hi[3]);
            }
            __syncthreads();

            float acc[4][4];
#pragma unroll
            for (int i = 0; i < 4; i++)
#pragma unroll
                for (int c = 0; c < 4; c++) acc[i][c] = 0.f;

#pragma unroll 4
            for (int k = 0; k < 64; k += 4) {
                float4 w0 = *(float4*)&u.s3.wt[(k + 0) * 36 + j0];
                float4 w1v = *(float4*)&u.s3.wt[(k + 1) * 36 + j0];
                float4 w2v = *(float4*)&u.s3.wt[(k + 2) * 36 + j0];
                float4 w3 = *(float4*)&u.s3.wt[(k + 3) * 36 + j0];
#pragma unroll
                for (int i = 0; i < 4; i++) {
                    float4 av = *(float4*)&u.s3.a[(rbase + i * 4) * 68 + k];
                    acc[i][0] = fmaf(av.x, w0.x, acc[i][0]);
                    acc[i][1] = fmaf(av.x, w0.y, acc[i][1]);
                    acc[i][2] = fmaf(av.x, w0.z, acc[i][2]);
                    acc[i][3] = fmaf(av.x, w0.w, acc[i][3]);
                    acc[i][0] = fmaf(av.y, w1v.x, acc[i][0]);
                    acc[i][1] = fmaf(av.y, w1v.y, acc[i][1]);
                    acc[i][2] = fmaf(av.y, w1v.z, acc[i][2]);
                    acc[i][3] = fmaf(av.y, w1v.w, acc[i][3]);
                    acc[i][0] = fmaf(av.z, w2v.x, acc[i][0]);
                    acc[i][1] = fmaf(av.z, w2v.y, acc[i][1]);
                    acc[i][2] = fmaf(av.z, w2v.z, acc[i][2]);
                    acc[i][3] = fmaf(av.z, w2v.w, acc[i][3]);
                    acc[i][0] = fmaf(av.w, w3.x, acc[i][0]);
                    acc[i][1] = fmaf(av.w, w3.y, acc[i][1]);
                    acc[i][2] = fmaf(av.w, w3.z, acc[i][2]);
                    acc[i][3] = fmaf(av.w, w3.w, acc[i][3]);
                }
            }

#pragma unroll
            for (int i = 0; i < 4; i++) {
                size_t r = base + rbase + i * 4;
                float v0 = acc[i][0] + bj[0];
                float v1 = acc[i][1] + bj[1];
                float v2 = acc[i][2] + bj[2];
                float v3 = acc[i][3] + bj[3];
                uint2 pk;
                pk.x = h2u(__floats2half2_rn(v0, v1));
                pk.y = h2u(__floats2half2_rn(v2, v3));
                *(uint2*)&g_h2h[r * 32 + j0] = pk;
                lsum[0] += v0; lsq[0] = fmaf(v0, v0, lsq[0]);
                lsum[1] += v1; lsq[1] = fmaf(v1, v1, lsq[1]);
                lsum[2] += v2; lsq[2] = fmaf(v2, v2, lsq[2]);
                lsum[3] += v3; lsq[3] = fmaf(v3, v3, lsq[3]);
            }
            __syncthreads();
        }

#pragma unroll
        for (int c = 0; c < 4; c++) {
            lsum[c] += __shfl_xor_sync(FULL, lsum[c], 8);
            lsum[c] += __shfl_xor_sync(FULL, lsum[c], 16);
            lsq[c] += __shfl_xor_sync(FULL, lsq[c], 8);
            lsq[c] += __shfl_xor_sync(FULL, lsq[c], 16);
        }
        if (tr == 0) {
#pragma unroll
            for (int c = 0; c < 4; c++) {
                u.s3.wsum[warp * 32 + j0 + c] = lsum[c];
                u.s3.wsq[warp * 32 + j0 + c] = lsq[c];
            }
        }
        __syncthreads();
        int t = tid;
        if (t < 32) {
            float s = 0.f;
#pragma unroll
            for (int w = 0; w < 8; w++) s += u.s3.wsum[w * 32 + t];
            g_part2[bid * 64 + t] = s;
        } else if (t < 64) {
            float q = 0.f;
#pragma unroll
            for (int w = 0; w < 8; w++) q += u.s3.wsq[w * 32 + (t - 32)];
            g_part2[bid * 64 + t] = q;
        }
    }

    // ---- barrier 2 (+ BN2 finalize by last block) ----
    __syncthreads();
    if (tid == 0) {
        __threadfence();
        unsigned tk = atomicAdd(&g_barA[2], 1u);
        s_tgt = (tk / GRIDu + 1u) * GRIDu;
        s_last = (tk % GRIDu == GRIDu - 1u) ? 1 : 0;
    }
    __syncthreads();
    if (s_last) {
        int t = tid;
        int ch = t & 63;
        int sl = t >> 6;   // 4 slices of 148 blocks
        float aa = 0.f;
        int b0 = sl * (GRID / 4);
        for (int b = b0; b < b0 + GRID / 4; b++) aa += g_part2[b * 64 + ch];
        u.fin[t] = aa;
        __syncthreads();
        if (t < 32) {
            float s = (u.fin[t] + u.fin[64 + t]) + (u.fin[128 + t] + u.fin[192 + t]);
            float q = (u.fin[32 + t] + u.fin[96 + t]) + (u.fin[160 + t] + u.fin[224 + t]);
            float mean = s / (float)NROWS;
            float var = q / (float)NROWS - mean * mean;
            float scale = g2[t] * rsqrtf(var + BN_EPS);
            g_bn2[t] = scale;
            g_bn2[32 + t] = beta2[t] - mean * scale;
        }
        __syncthreads();
        if (tid == 0) { __threadfence(); atomicAdd(&g_barR[2], GRIDu); }
    } else if (tid == 0) {
        while (atomicAdd(&g_barR[2], 0u) < s_tgt) __nanosleep(64);
        __threadfence();
    }
    __syncthreads();

    // ===== Phase 3: out += relu(bn2(h2)) @ wout^T + bout =====
    {
        int tr = lane >> 3, tj = lane & 7;
        int j0 = tj * 4;
        for (int i = tid; i < 1024; i += 256) {
            int j = i >> 5, k = i & 31;
            u.s5.wt[k * 36 + j] = wout[i];
        }
        if (tid < 32) { u.s5.sc[tid] = g_bn2[tid]; u.s5.sh[tid] = g_bn2[32 + tid]; }
        float bj[4];
#pragma unroll
        for (int c = 0; c < 4; c++) bj[c] = bout[j0 + c];
        __syncthreads();

        int rbase = warp * 16 + tr;

        for (int tile = bid; tile < N_TILES; tile += GRID) {
            size_t base = (size_t)tile * TILE_R;
            for (int i = tid; i < TILE_R * 4; i += 256) {
                int r = i >> 2, c8 = (i & 3) * 8;
                uint4 raw = *(const uint4*)&g_h2h[(base + r) * 32 + c8];
                const __half2* hp = (const __half2*)&raw;
                float f[8];
#pragma unroll
                for (int m = 0; m < 4; m++) {
                    float2 p = __half22float2(hp[m]);
                    f[2 * m] = p.x;
                    f[2 * m + 1] = p.y;
                }
#pragma unroll
                for (int m = 0; m < 8; m++)
                    f[m] = fmaxf(fmaf(f[m], u.s5.sc[c8 + m], u.s5.sh[c8 + m]), 0.f);
                *(float4*)&u.s5.a[r * 36 + c8] = make_float4(f[0], f[1], f[2], f[3]);
                *(float4*)&u.s5.a[r * 36 + c8 + 4] = make_float4(f[4], f[5], f[6], f[7]);
            }
            __syncthreads();

            float acc[4][4];
#pragma unroll
            for (int i = 0; i < 4; i++)
#pragma unroll
                for (int c = 0; c < 4; c++) acc[i][c] = 0.f;

#pragma unroll 4
            for (int k = 0; k < 32; k += 4) {
                float4 w0 = *(float4*)&u.s5.wt[(k + 0) * 36 + j0];
                float4 w1v = *(float4*)&u.s5.wt[(k + 1) * 36 + j0];
                float4 w2v = *(float4*)&u.s5.wt[(k + 2) * 36 + j0];
                float4 w3 = *(float4*)&u.s5.wt[(k + 3) * 36 + j0];
#pragma unroll
                for (int i = 0; i < 4; i++) {
                    float4 av = *(float4*)&u.s5.a[(rbase + i * 4) * 36 + k];
                    acc[i][0] = fmaf(av.x, w0.x, acc[i][0]);
                    acc[i][1] = fmaf(av.x, w0.y, acc[i][1]);
                    acc[i][2] = fmaf(av.x, w0.z, acc[i][2]);
                    acc[i][3] = fmaf(av.x, w0.w, acc[i][3]);
                    acc[i][0] = fmaf(av.y, w1v.x, acc[i][0]);
                    acc[i][1] = fmaf(av.y, w1v.y, acc[i][1]);
                    acc[i][2] = fmaf(av.y, w1v.z, acc[i][2]);
                    acc[i][3] = fmaf(av.y, w1v.w, acc[i][3]);
                    acc[i][0] = fmaf(av.z, w2v.x, acc[i][0]);
                    acc[i][1] = fmaf(av.z, w2v.y, acc[i][1]);
                    acc[i][2] = fmaf(av.z, w2v.z, acc[i][2]);
                    acc[i][3] = fmaf(av.z, w2v.w, acc[i][3]);
                    acc[i][0] = fmaf(av.w, w3.x, acc[i][0]);
                    acc[i][1] = fmaf(av.w, w3.y, acc[i][1]);
                    acc[i][2] = fmaf(av.w, w3.z, acc[i][2]);
                    acc[i][3] = fmaf(av.w, w3.w, acc[i][3]);
                }
            }

#pragma unroll
            for (int i = 0; i < 4; i++) {
                size_t r = base + rbase + i * 4;
                float4 o = *(const float4*)&out[r * 32 + j0];
                o.x += acc[i][0] + bj[0];
                o.y += acc[i][1] + bj[1];
                o.z += acc[i][2] + bj[2];
                o.w += acc[i][3] + bj[3];
                *(float4*)&out[r * 32 + j0] = o;
            }
            __syncthreads();
        }
    }
}

// ---------------------------------------------------------------------------
// Input order (setup_inputs dict insertion): x, emb0, lin0, emb1, lin1,
// emb2, lin2, emb3, lin3, cont_w, cont_b, clin_w, clin_b, fin_bias,
// w1, b1, g1, beta1, w2, b2, g2, beta2, w_out, b_out
// ---------------------------------------------------------------------------
extern "C" void kernel_launch(void* const* d_in, const int* in_sizes, int n_in,
                              void* d_out, int out_size) {
    const float* x      = (const float*)d_in[0];
    const float* emb0   = (const float*)d_in[1];
    const float* lin0   = (const float*)d_in[2];
    const float* emb1   = (const float*)d_in[3];
    const float* lin1   = (const float*)d_in[4];
    const float* emb2   = (const float*)d_in[5];
    const float* lin2   = (const float*)d_in[6];
    const float* emb3   = (const float*)d_in[7];
    const float* lin3   = (const float*)d_in[8];
    const float* cont_w = (const float*)d_in[9];
    const float* cont_b = (const float*)d_in[10];
    const float* clin_w = (const float*)d_in[11];
    const float* clin_b = (const float*)d_in[12];
    const float* fin_b  = (const float*)d_in[13];
    const float* w1     = (const float*)d_in[14];
    const float* b1     = (const float*)d_in[15];
    const float* g1     = (const float*)d_in[16];
    const float* beta1  = (const float*)d_in[17];
    const float* w2     = (const float*)d_in[18];
    const float* b2     = (const float*)d_in[19];
    const float* g2     = (const float*)d_in[20];
    const float* beta2  = (const float*)d_in[21];
    const float* w_out  = (const float*)d_in[22];
    const float* b_out  = (const float*)d_in[23];
    float* out = (float*)d_out;

    kFused<<<GRID, 256>>>(x, emb0, lin0, emb1, lin1, emb2, lin2, emb3, lin3,
                          cont_w, cont_b, clin_w, clin_b, fin_b,
                          w1, b1, g1, beta1, w2, b2, g2, beta2,
                          w_out, b_out, out);
}